// round 4
// baseline (speedup 1.0000x reference)
#include <cuda_runtime.h>
#include <cuda_bf16.h>
#include <cuda_fp8.h>
#include <cstdint>

// Problem constants (fixed by setup_inputs)
#define NE   8
#define DOUT 2048
#define DIN  2048
#define SEQ  8192
#define GRP  128
#define KBLK (DIN / GRP)    // 16 K-blocks
#define NBLK (DOUT / GRP)   // 16 N-blocks

// Scratch: quantized values stored as bf16 (every e4m3 value is exact in bf16),
// plus per-tile / per-block fp32 scales.
__device__ __align__(16) __nv_bfloat16 g_xq[SEQ * DIN];              // 32 MB
__device__ __align__(16) float         g_xs[SEQ * KBLK];             // 512 KB
__device__ __align__(16) __nv_bfloat16 g_wq[NE * DOUT * DIN];        // 64 MB
__device__ __align__(16) float         g_ws[NE * NBLK * KBLK];       // 8 KB

// fp8 e4m3 quantize-dequantize, matching jnp clip -> astype(e4m3, RN) -> fp32
__device__ __forceinline__ float qdq_e4m3(float v, float scale) {
    float c = fminf(fmaxf(v / scale, -448.0f), 448.0f);
    __nv_fp8_e4m3 q(c);   // RN, satfinite
    return (float)q;
}

__device__ __forceinline__ uint32_t pack_bf16x2(float a, float b) {
    __nv_bfloat162 h = __floats2bfloat162_rn(a, b);  // exact: inputs are e4m3 grid values
    return *reinterpret_cast<uint32_t*>(&h);
}

// ---------------------------------------------------------------------------
// Kernel 1: per 1x128 tile activation quant. One warp per tile.
// ---------------------------------------------------------------------------
__global__ __launch_bounds__(256) void quant_x_kernel(const float* __restrict__ x) {
    int warp = threadIdx.x >> 5;
    int lane = threadIdx.x & 31;
    int tile = blockIdx.x * 8 + warp;                 // tile = row*KBLK + kb
    const float4 v = *reinterpret_cast<const float4*>(x + (size_t)tile * GRP + lane * 4);

    float a = fmaxf(fmaxf(fabsf(v.x), fabsf(v.y)), fmaxf(fabsf(v.z), fabsf(v.w)));
#pragma unroll
    for (int o = 16; o; o >>= 1) a = fmaxf(a, __shfl_xor_sync(0xffffffffu, a, o));
    float scale = fmaxf(a, 1e-12f) / 448.0f;

    float q0 = qdq_e4m3(v.x, scale);
    float q1 = qdq_e4m3(v.y, scale);
    float q2 = qdq_e4m3(v.z, scale);
    float q3 = qdq_e4m3(v.w, scale);

    uint2 out;
    out.x = pack_bf16x2(q0, q1);
    out.y = pack_bf16x2(q2, q3);
    *reinterpret_cast<uint2*>(g_xq + (size_t)tile * GRP + lane * 4) = out;

    if (lane == 0) g_xs[tile] = scale;
}

// ---------------------------------------------------------------------------
// Kernel 2: per 128x128 block weight quant. One 256-thread CTA per block.
// ---------------------------------------------------------------------------
__global__ __launch_bounds__(256) void quant_w_kernel(const float* __restrict__ w) {
    int b   = blockIdx.x;          // NE*NBLK*KBLK = 2048 blocks
    int e   = b >> 8;
    int rem = b & 255;
    int nb  = rem >> 4;
    int kb  = rem & 15;

    const size_t base = ((size_t)(e * DOUT + nb * GRP)) * DIN + kb * GRP;
    const float* src = w + base;
    __nv_bfloat16* dst = g_wq + base;

    int tid  = threadIdx.x;
    int lane = tid & 31;
    int warp = tid >> 5;

    // Pass 1: amax over the 128x128 block (4096 float4)
    float a = 0.0f;
#pragma unroll
    for (int i = tid; i < 4096; i += 256) {
        int r = i >> 5, c = i & 31;
        float4 v = *reinterpret_cast<const float4*>(src + (size_t)r * DIN + c * 4);
        a = fmaxf(a, fmaxf(fmaxf(fabsf(v.x), fabsf(v.y)), fmaxf(fabsf(v.z), fabsf(v.w))));
    }
#pragma unroll
    for (int o = 16; o; o >>= 1) a = fmaxf(a, __shfl_xor_sync(0xffffffffu, a, o));

    __shared__ float red[8];
    __shared__ float s_scale;
    if (lane == 0) red[warp] = a;
    __syncthreads();
    if (tid == 0) {
        float m = red[0];
#pragma unroll
        for (int i = 1; i < 8; i++) m = fmaxf(m, red[i]);
        s_scale = fmaxf(m, 1e-12f) / 448.0f;
    }
    __syncthreads();
    float scale = s_scale;

    // Pass 2: re-read (L2-hot), quantize, store bf16
#pragma unroll
    for (int i = tid; i < 4096; i += 256) {
        int r = i >> 5, c = i & 31;
        float4 v = *reinterpret_cast<const float4*>(src + (size_t)r * DIN + c * 4);
        uint2 o;
        o.x = pack_bf16x2(qdq_e4m3(v.x, scale), qdq_e4m3(v.y, scale));
        o.y = pack_bf16x2(qdq_e4m3(v.z, scale), qdq_e4m3(v.w, scale));
        *reinterpret_cast<uint2*>(dst + (size_t)r * DIN + c * 4) = o;
    }
    if (tid == 0) g_ws[(e * NBLK + nb) * KBLK + kb] = scale;
}

// ---------------------------------------------------------------------------
// Kernel 3: grouped block-scaled GEMM. 128x128 tile, BK=32, bf16 mma.sync.
// ---------------------------------------------------------------------------
#define BM   128
#define BN   128
#define BK   32
#define LDS_ 40    // padded smem row stride in halves (80B -> conflict-free ldmatrix)

__device__ __forceinline__ void cp16(uint32_t dst, const void* src, int src_bytes) {
    asm volatile("cp.async.cg.shared.global [%0], [%1], 16, %2;\n"
                 :: "r"(dst), "l"(src), "r"(src_bytes) : "memory");
}
__device__ __forceinline__ void ldm_x4(uint32_t r[4], uint32_t addr) {
    asm volatile("ldmatrix.sync.aligned.m8n8.x4.shared.b16 {%0,%1,%2,%3}, [%4];"
                 : "=r"(r[0]), "=r"(r[1]), "=r"(r[2]), "=r"(r[3]) : "r"(addr));
}
__device__ __forceinline__ void mma16816(float c[4], const uint32_t a[4], const uint32_t b[2]) {
    asm volatile(
        "mma.sync.aligned.m16n8k16.row.col.f32.bf16.bf16.f32 "
        "{%0,%1,%2,%3}, {%4,%5,%6,%7}, {%8,%9}, {%0,%1,%2,%3};"
        : "+f"(c[0]), "+f"(c[1]), "+f"(c[2]), "+f"(c[3])
        : "r"(a[0]), "r"(a[1]), "r"(a[2]), "r"(a[3]), "r"(b[0]), "r"(b[1]));
}

__global__ __launch_bounds__(256, 1) void gemm_kernel(float* __restrict__ out,
                                                      const int* __restrict__ tpe) {
    __shared__ __align__(16) __nv_bfloat16 As[2][BM * LDS_];
    __shared__ __align__(16) __nv_bfloat16 Bs[2][BN * LDS_];

    const int tid  = threadIdx.x;
    const int lane = tid & 31;
    const int wrp  = tid >> 5;
    const int wm   = wrp & 3;   // 4 warps along M (32 rows each)
    const int wn   = wrp >> 2;  // 2 warps along N (64 cols each)

    const int m0 = blockIdx.y * BM;
    const int n0 = blockIdx.x * BN;

    // Expert lookup via on-device prefix sum (8 experts)
    int accv = 0, e = -1, rs = 0, re = 0;
#pragma unroll
    for (int i = 0; i < NE; i++) {
        int c = tpe[i];
        if (e < 0 && m0 >= accv && m0 < accv + c) { e = i; rs = accv; re = accv + c; }
        accv += c;
    }
    if (e < 0) return;  // uncovered rows stay at the memset zeros

    const __nv_bfloat16* Aptr = g_xq;
    const __nv_bfloat16* Bptr = g_wq + (size_t)e * DOUT * DIN;

    // cp.async stage loader: 512 A chunks + 512 B chunks of 16B, 2 per thread each
    auto load_stage = [&](int kt, int st) {
        int kc = kt * BK;
#pragma unroll
        for (int i = 0; i < 2; i++) {
            int cid = tid + 256 * i;
            int row = cid >> 2;
            int cc  = cid & 3;
            // A (with expert-range zero-fill)
            int gr = m0 + row;
            const void* asrc = Aptr + (size_t)gr * DIN + kc + cc * 8;
            uint32_t adst = (uint32_t)__cvta_generic_to_shared(&As[st][row * LDS_ + cc * 8]);
            cp16(adst, asrc, (gr >= rs && gr < re) ? 16 : 0);
            // B
            const void* bsrc = Bptr + (size_t)(n0 + row) * DIN + kc + cc * 8;
            uint32_t bdst = (uint32_t)__cvta_generic_to_shared(&Bs[st][row * LDS_ + cc * 8]);
            cp16(bdst, bsrc, 16);
        }
        asm volatile("cp.async.commit_group;\n" ::: "memory");
    };

    float tot[2][8][4];
    float par[2][8][4];
#pragma unroll
    for (int mi = 0; mi < 2; mi++)
#pragma unroll
        for (int ni = 0; ni < 8; ni++)
#pragma unroll
            for (int q = 0; q < 4; q++) { tot[mi][ni][q] = 0.f; par[mi][ni][q] = 0.f; }

    load_stage(0, 0);
    const int KT = DIN / BK;  // 64

#pragma unroll 1
    for (int kb = 0; kb < KBLK; kb++) {
#pragma unroll
        for (int ki = 0; ki < 4; ki++) {
            int kt = kb * 4 + ki;
            int st = kt & 1;
            if (kt + 1 < KT) {
                load_stage(kt + 1, st ^ 1);
                asm volatile("cp.async.wait_group 1;\n" ::: "memory");
            } else {
                asm volatile("cp.async.wait_group 0;\n" ::: "memory");
            }
            __syncthreads();

#pragma unroll
            for (int ks = 0; ks < 2; ks++) {
                const int k0 = ks * 16;
                uint32_t af[2][4];
#pragma unroll
                for (int mi = 0; mi < 2; mi++) {
                    int row = wm * 32 + mi * 16 + (lane & 15);
                    int col = k0 + ((lane >> 4) << 3);
                    uint32_t addr = (uint32_t)__cvta_generic_to_shared(&As[st][row * LDS_ + col]);
                    ldm_x4(af[mi], addr);
                }
                uint32_t bf[8][2];
#pragma unroll
                for (int nj = 0; nj < 4; nj++) {
                    int g = lane >> 3;
                    int n = wn * 64 + nj * 16 + ((g >> 1) << 3) + (lane & 7);
                    int kk = k0 + ((g & 1) << 3);
                    uint32_t addr = (uint32_t)__cvta_generic_to_shared(&Bs[st][n * LDS_ + kk]);
                    uint32_t r[4];
                    ldm_x4(r, addr);
                    bf[nj * 2 + 0][0] = r[0]; bf[nj * 2 + 0][1] = r[1];
                    bf[nj * 2 + 1][0] = r[2]; bf[nj * 2 + 1][1] = r[3];
                }
#pragma unroll
                for (int mi = 0; mi < 2; mi++)
#pragma unroll
                    for (int ni = 0; ni < 8; ni++)
                        mma16816(par[mi][ni], af[mi], bf[ni]);
            }
            __syncthreads();
        }

        // End of one 128-wide K-block: fold scales into the fp32 total
        const float sw = g_ws[(e * NBLK + (n0 >> 7)) * KBLK + kb];
#pragma unroll
        for (int mi = 0; mi < 2; mi++) {
            int r0 = m0 + wm * 32 + mi * 16 + (lane >> 2);
            float sx0 = g_xs[r0 * KBLK + kb] * sw;
            float sx1 = g_xs[(r0 + 8) * KBLK + kb] * sw;
#pragma unroll
            for (int ni = 0; ni < 8; ni++) {
                tot[mi][ni][0] = fmaf(par[mi][ni][0], sx0, tot[mi][ni][0]);
                tot[mi][ni][1] = fmaf(par[mi][ni][1], sx0, tot[mi][ni][1]);
                tot[mi][ni][2] = fmaf(par[mi][ni][2], sx1, tot[mi][ni][2]);
                tot[mi][ni][3] = fmaf(par[mi][ni][3], sx1, tot[mi][ni][3]);
                par[mi][ni][0] = 0.f; par[mi][ni][1] = 0.f;
                par[mi][ni][2] = 0.f; par[mi][ni][3] = 0.f;
            }
        }
    }

    // Epilogue: fp32 stores (only rows owned by this expert)
#pragma unroll
    for (int mi = 0; mi < 2; mi++) {
        int r0 = m0 + wm * 32 + mi * 16 + (lane >> 2);
        int r1 = r0 + 8;
#pragma unroll
        for (int ni = 0; ni < 8; ni++) {
            int col = n0 + wn * 64 + ni * 8 + ((lane & 3) << 1);
            if (r0 >= rs && r0 < re) {
                float2 v0 = {tot[mi][ni][0], tot[mi][ni][1]};
                *reinterpret_cast<float2*>(out + (size_t)r0 * DOUT + col) = v0;
            }
            if (r1 >= rs && r1 < re) {
                float2 v1 = {tot[mi][ni][2], tot[mi][ni][3]};
                *reinterpret_cast<float2*>(out + (size_t)r1 * DOUT + col) = v1;
            }
        }
    }
}

// ---------------------------------------------------------------------------
extern "C" void kernel_launch(void* const* d_in, const int* in_sizes, int n_in,
                              void* d_out, int out_size) {
    const float* x   = (const float*)d_in[0];
    const float* w   = (const float*)d_in[1];
    const int*   tpe = (const int*)d_in[2];
    float* out = (float*)d_out;

    cudaMemsetAsync(d_out, 0, (size_t)out_size * sizeof(float));

    quant_x_kernel<<<SEQ * KBLK / 8, 256>>>(x);
    quant_w_kernel<<<NE * NBLK * KBLK, 256>>>(w);
    gemm_kernel<<<dim3(DOUT / BN, SEQ / BM), 256>>>(out, tpe);
}

// round 5
// speedup vs baseline: 1.1825x; 1.1825x over previous
#include <cuda_runtime.h>
#include <cuda_bf16.h>
#include <cuda_fp8.h>
#include <cstdint>

// Problem constants (fixed by setup_inputs)
#define NE   8
#define DOUT 2048
#define DIN  2048
#define SEQ  8192
#define GRP  128
#define KBLK (DIN / GRP)    // 16 K-blocks
#define NBLK (DOUT / GRP)   // 16 N-blocks

// Scratch: quantized values stored as raw e4m3 bytes + fp32 scales.
__device__ __align__(16) uint8_t g_xq[SEQ * DIN];              // 16 MB
__device__ __align__(16) float   g_xs[SEQ * KBLK];             // 512 KB
__device__ __align__(16) uint8_t g_wq[NE * DOUT * DIN];        // 32 MB
__device__ __align__(16) float   g_ws[NE * NBLK * KBLK];       // 8 KB

// fp8 e4m3 quantize: clip+RN == RN-satfinite convert of v/scale
__device__ __forceinline__ uint32_t quant4_e4m3(float4 v, float scale) {
    float4 c = make_float4(v.x / scale, v.y / scale, v.z / scale, v.w / scale);
    __nv_fp8x4_e4m3 q(c);   // RN, satfinite (== clip to +-448 then RN)
    return *reinterpret_cast<uint32_t*>(&q);
}

// ---------------------------------------------------------------------------
// Kernel 1: per 1x128 tile activation quant. One warp per tile.
// ---------------------------------------------------------------------------
__global__ __launch_bounds__(256) void quant_x_kernel(const float* __restrict__ x) {
    int warp = threadIdx.x >> 5;
    int lane = threadIdx.x & 31;
    int tile = blockIdx.x * 8 + warp;                 // tile = row*KBLK + kb
    const float4 v = *reinterpret_cast<const float4*>(x + (size_t)tile * GRP + lane * 4);

    float a = fmaxf(fmaxf(fabsf(v.x), fabsf(v.y)), fmaxf(fabsf(v.z), fabsf(v.w)));
#pragma unroll
    for (int o = 16; o; o >>= 1) a = fmaxf(a, __shfl_xor_sync(0xffffffffu, a, o));
    float scale = fmaxf(a, 1e-12f) / 448.0f;

    *reinterpret_cast<uint32_t*>(g_xq + (size_t)tile * GRP + lane * 4) = quant4_e4m3(v, scale);
    if (lane == 0) g_xs[tile] = scale;
}

// ---------------------------------------------------------------------------
// Kernel 2: per 128x128 block weight quant. One 256-thread CTA per block.
// ---------------------------------------------------------------------------
__global__ __launch_bounds__(256) void quant_w_kernel(const float* __restrict__ w) {
    int b   = blockIdx.x;          // NE*NBLK*KBLK = 2048 blocks
    int e   = b >> 8;
    int rem = b & 255;
    int nb  = rem >> 4;
    int kb  = rem & 15;

    const size_t base = ((size_t)(e * DOUT + nb * GRP)) * DIN + kb * GRP;
    const float* src = w + base;
    uint8_t* dst = g_wq + base;

    int tid  = threadIdx.x;
    int lane = tid & 31;
    int warp = tid >> 5;

    // Pass 1: amax over the 128x128 block (4096 float4)
    float a = 0.0f;
#pragma unroll
    for (int i = tid; i < 4096; i += 256) {
        int r = i >> 5, c = i & 31;
        float4 v = *reinterpret_cast<const float4*>(src + (size_t)r * DIN + c * 4);
        a = fmaxf(a, fmaxf(fmaxf(fabsf(v.x), fabsf(v.y)), fmaxf(fabsf(v.z), fabsf(v.w))));
    }
#pragma unroll
    for (int o = 16; o; o >>= 1) a = fmaxf(a, __shfl_xor_sync(0xffffffffu, a, o));

    __shared__ float red[8];
    __shared__ float s_scale;
    if (lane == 0) red[warp] = a;
    __syncthreads();
    if (tid == 0) {
        float m = red[0];
#pragma unroll
        for (int i = 1; i < 8; i++) m = fmaxf(m, red[i]);
        s_scale = fmaxf(m, 1e-12f) / 448.0f;
    }
    __syncthreads();
    float scale = s_scale;

    // Pass 2: re-read (L2-hot), quantize, store fp8 bytes
#pragma unroll
    for (int i = tid; i < 4096; i += 256) {
        int r = i >> 5, c = i & 31;
        float4 v = *reinterpret_cast<const float4*>(src + (size_t)r * DIN + c * 4);
        *reinterpret_cast<uint32_t*>(dst + (size_t)r * DIN + c * 4) = quant4_e4m3(v, scale);
    }
    if (tid == 0) g_ws[(e * NBLK + nb) * KBLK + kb] = scale;
}

// ---------------------------------------------------------------------------
// Kernel 3: grouped block-scaled GEMM. 128x128 tile, BK=64 bytes, fp8 QMMA.
// ---------------------------------------------------------------------------
#define BM    128
#define BN    128
#define BK    64                  // fp8 elements (= bytes) per stage
#define LDSB  80                  // padded smem row stride in bytes (conflict-free)
#define STG   4                   // pipeline depth
#define ASTAGE (BM * LDSB)        // 10240 B
#define SMEM_BYTES (2 * STG * ASTAGE)  // 81920 B

__device__ __forceinline__ void cp16(uint32_t dst, const void* src, int src_bytes) {
    asm volatile("cp.async.cg.shared.global [%0], [%1], 16, %2;\n"
                 :: "r"(dst), "l"(src), "r"(src_bytes) : "memory");
}
__device__ __forceinline__ void ldm_x4(uint32_t r[4], uint32_t addr) {
    asm volatile("ldmatrix.sync.aligned.m8n8.x4.shared.b16 {%0,%1,%2,%3}, [%4];"
                 : "=r"(r[0]), "=r"(r[1]), "=r"(r[2]), "=r"(r[3]) : "r"(addr));
}
__device__ __forceinline__ void mma_fp8(float c[4], const uint32_t a[4], const uint32_t b[2]) {
    asm volatile(
        "mma.sync.aligned.m16n8k32.row.col.f32.e4m3.e4m3.f32 "
        "{%0,%1,%2,%3}, {%4,%5,%6,%7}, {%8,%9}, {%0,%1,%2,%3};"
        : "+f"(c[0]), "+f"(c[1]), "+f"(c[2]), "+f"(c[3])
        : "r"(a[0]), "r"(a[1]), "r"(a[2]), "r"(a[3]), "r"(b[0]), "r"(b[1]));
}

__global__ __launch_bounds__(256, 1) void gemm_kernel(float* __restrict__ out,
                                                      const int* __restrict__ tpe) {
    extern __shared__ __align__(16) uint8_t smem[];
    uint8_t* As = smem;                    // STG stages of 128 x 64B (stride 80)
    uint8_t* Bs = smem + STG * ASTAGE;

    const int tid  = threadIdx.x;
    const int lane = tid & 31;
    const int wrp  = tid >> 5;
    const int wm   = wrp & 3;   // 4 warps along M (32 rows each)
    const int wn   = wrp >> 2;  // 2 warps along N (64 cols each)

    const int m0 = blockIdx.y * BM;
    const int n0 = blockIdx.x * BN;

    // Expert lookup via on-device prefix sum (8 experts)
    int accv = 0, e = -1, rs = 0, re = 0;
#pragma unroll
    for (int i = 0; i < NE; i++) {
        int c = tpe[i];
        if (e < 0 && m0 >= accv && m0 < accv + c) { e = i; rs = accv; re = accv + c; }
        accv += c;
    }
    if (e < 0) { e = 0; rs = 0; re = 0; }   // tile fully zero-filled -> stores zeros

    const uint8_t* Aptr = g_xq;
    const uint8_t* Bptr = g_wq + (size_t)e * DOUT * DIN;

    // Stage loader: 512 A chunks + 512 B chunks of 16B, 2 each per thread
    auto load_stage = [&](int kt, int st) {
        int kc = kt * BK;
#pragma unroll
        for (int i = 0; i < 2; i++) {
            int cid = tid + 256 * i;
            int row = cid >> 2;
            int cc  = (cid & 3) * 16;
            // A (expert-range zero-fill)
            int gr = m0 + row;
            const void* asrc = Aptr + (size_t)gr * DIN + kc + cc;
            uint32_t adst = (uint32_t)__cvta_generic_to_shared(As + st * ASTAGE + row * LDSB + cc);
            cp16(adst, asrc, (gr >= rs && gr < re) ? 16 : 0);
            // B
            const void* bsrc = Bptr + (size_t)(n0 + row) * DIN + kc + cc;
            uint32_t bdst = (uint32_t)__cvta_generic_to_shared(Bs + st * ASTAGE + row * LDSB + cc);
            cp16(bdst, bsrc, 16);
        }
        asm volatile("cp.async.commit_group;\n" ::: "memory");
    };

    float tot[2][8][4];
    float par[2][8][4];
#pragma unroll
    for (int mi = 0; mi < 2; mi++)
#pragma unroll
        for (int ni = 0; ni < 8; ni++)
#pragma unroll
            for (int q = 0; q < 4; q++) { tot[mi][ni][q] = 0.f; par[mi][ni][q] = 0.f; }

    const int KT = DIN / BK;  // 32 stages over K
    load_stage(0, 0);
    load_stage(1, 1);
    load_stage(2, 2);

#pragma unroll 1
    for (int kt = 0; kt < KT; kt++) {
        const int st = kt & (STG - 1);

        asm volatile("cp.async.wait_group 2;\n" ::: "memory");
        __syncthreads();

        // Refill the slot computed last iteration (all warps past it via the sync)
        if (kt + 3 < KT) load_stage(kt + 3, (kt + 3) & (STG - 1));
        else             asm volatile("cp.async.commit_group;\n" ::: "memory");

        // Compute this stage: 2 k-steps of k=32 fp8
#pragma unroll
        for (int ks = 0; ks < 2; ks++) {
            const int k0 = ks * 32;   // byte offset
            uint32_t af[2][4];
#pragma unroll
            for (int mi = 0; mi < 2; mi++) {
                int row = wm * 32 + mi * 16 + (lane & 15);
                int col = k0 + ((lane >> 4) << 4);
                uint32_t addr = (uint32_t)__cvta_generic_to_shared(As + st * ASTAGE + row * LDSB + col);
                ldm_x4(af[mi], addr);
            }
            uint32_t bf[8][2];
#pragma unroll
            for (int nj = 0; nj < 4; nj++) {
                int g = lane >> 3;
                int n = wn * 64 + nj * 16 + ((g >> 1) << 3) + (lane & 7);
                int kk = k0 + ((g & 1) << 4);
                uint32_t addr = (uint32_t)__cvta_generic_to_shared(Bs + st * ASTAGE + n * LDSB + kk);
                uint32_t r[4];
                ldm_x4(r, addr);
                bf[nj * 2 + 0][0] = r[0]; bf[nj * 2 + 0][1] = r[1];
                bf[nj * 2 + 1][0] = r[2]; bf[nj * 2 + 1][1] = r[3];
            }
#pragma unroll
            for (int mi = 0; mi < 2; mi++)
#pragma unroll
                for (int ni = 0; ni < 8; ni++)
                    mma_fp8(par[mi][ni], af[mi], bf[ni]);
        }

        // Every 2 stages = one 128-wide K-block: fold scales into fp32 total
        if (kt & 1) {
            const int kb = kt >> 1;
            const float sw = g_ws[(e * NBLK + (n0 >> 7)) * KBLK + kb];
#pragma unroll
            for (int mi = 0; mi < 2; mi++) {
                int r0 = m0 + wm * 32 + mi * 16 + (lane >> 2);
                float sx0 = g_xs[r0 * KBLK + kb] * sw;
                float sx1 = g_xs[(r0 + 8) * KBLK + kb] * sw;
#pragma unroll
                for (int ni = 0; ni < 8; ni++) {
                    tot[mi][ni][0] = fmaf(par[mi][ni][0], sx0, tot[mi][ni][0]);
                    tot[mi][ni][1] = fmaf(par[mi][ni][1], sx0, tot[mi][ni][1]);
                    tot[mi][ni][2] = fmaf(par[mi][ni][2], sx1, tot[mi][ni][2]);
                    tot[mi][ni][3] = fmaf(par[mi][ni][3], sx1, tot[mi][ni][3]);
                    par[mi][ni][0] = 0.f; par[mi][ni][1] = 0.f;
                    par[mi][ni][2] = 0.f; par[mi][ni][3] = 0.f;
                }
            }
        }
    }

    // Epilogue: fp32 stores; rows outside this tile's expert range get zeros
    // (grid covers all of out, so no memset is needed).
#pragma unroll
    for (int mi = 0; mi < 2; mi++) {
        int r0 = m0 + wm * 32 + mi * 16 + (lane >> 2);
        int r1 = r0 + 8;
        bool in0 = (r0 >= rs && r0 < re);
        bool in1 = (r1 >= rs && r1 < re);
#pragma unroll
        for (int ni = 0; ni < 8; ni++) {
            int col = n0 + wn * 64 + ni * 8 + ((lane & 3) << 1);
            float2 v0 = {in0 ? tot[mi][ni][0] : 0.f, in0 ? tot[mi][ni][1] : 0.f};
            float2 v1 = {in1 ? tot[mi][ni][2] : 0.f, in1 ? tot[mi][ni][3] : 0.f};
            *reinterpret_cast<float2*>(out + (size_t)r0 * DOUT + col) = v0;
            *reinterpret_cast<float2*>(out + (size_t)r1 * DOUT + col) = v1;
        }
    }
}

// ---------------------------------------------------------------------------
extern "C" void kernel_launch(void* const* d_in, const int* in_sizes, int n_in,
                              void* d_out, int out_size) {
    const float* x   = (const float*)d_in[0];
    const float* w   = (const float*)d_in[1];
    const int*   tpe = (const int*)d_in[2];
    float* out = (float*)d_out;

    cudaFuncSetAttribute(gemm_kernel, cudaFuncAttributeMaxDynamicSharedMemorySize, SMEM_BYTES);

    quant_x_kernel<<<SEQ * KBLK / 8, 256>>>(x);
    quant_w_kernel<<<NE * NBLK * KBLK, 256>>>(w);
    gemm_kernel<<<dim3(DOUT / BN, SEQ / BM), 256, SMEM_BYTES>>>(out, tpe);
}

// round 7
// speedup vs baseline: 1.4304x; 1.2097x over previous
#include <cuda_runtime.h>
#include <cuda_bf16.h>
#include <cuda_fp8.h>
#include <cstdint>

// Problem constants (fixed by setup_inputs)
#define NE   8
#define DOUT 2048
#define DIN  2048
#define SEQ  8192
#define GRP  128
#define KBLK (DIN / GRP)    // 16 K-blocks
#define NBLK (DOUT / GRP)   // 16 N-blocks

// Scratch: quantized values stored as raw e4m3 bytes + fp32 scales.
__device__ __align__(16) uint8_t g_xq[SEQ * DIN];              // 16 MB
__device__ __align__(16) float   g_xs[SEQ * KBLK];             // 512 KB
__device__ __align__(16) uint8_t g_wq[NE * DOUT * DIN];        // 32 MB
__device__ __align__(16) float   g_ws[NE * NBLK * KBLK];       // 8 KB

// fp8 e4m3 quantize: clip+RN == RN-satfinite convert of v/scale
__device__ __forceinline__ uint32_t quant4_e4m3(float4 v, float scale) {
    float4 c = make_float4(v.x / scale, v.y / scale, v.z / scale, v.w / scale);
    __nv_fp8x4_e4m3 q(c);   // RN, satfinite (== clip to +-448 then RN)
    return *reinterpret_cast<uint32_t*>(&q);
}

// ---------------------------------------------------------------------------
// Kernel 1: per 1x128 tile activation quant. Two tiles per warp (MLP=2).
// ---------------------------------------------------------------------------
__global__ __launch_bounds__(256) void quant_x_kernel(const float* __restrict__ x) {
    int warp = threadIdx.x >> 5;
    int lane = threadIdx.x & 31;
    int t0 = (blockIdx.x * 8 + warp) * 2;             // two consecutive tiles

    const float4 v0 = *reinterpret_cast<const float4*>(x + (size_t)t0 * GRP + lane * 4);
    const float4 v1 = *reinterpret_cast<const float4*>(x + (size_t)(t0 + 1) * GRP + lane * 4);

    float a0 = fmaxf(fmaxf(fabsf(v0.x), fabsf(v0.y)), fmaxf(fabsf(v0.z), fabsf(v0.w)));
    float a1 = fmaxf(fmaxf(fabsf(v1.x), fabsf(v1.y)), fmaxf(fabsf(v1.z), fabsf(v1.w)));
#pragma unroll
    for (int o = 16; o; o >>= 1) {
        a0 = fmaxf(a0, __shfl_xor_sync(0xffffffffu, a0, o));
        a1 = fmaxf(a1, __shfl_xor_sync(0xffffffffu, a1, o));
    }
    float s0 = fmaxf(a0, 1e-12f) / 448.0f;
    float s1 = fmaxf(a1, 1e-12f) / 448.0f;

    *reinterpret_cast<uint32_t*>(g_xq + (size_t)t0 * GRP + lane * 4)       = quant4_e4m3(v0, s0);
    *reinterpret_cast<uint32_t*>(g_xq + (size_t)(t0 + 1) * GRP + lane * 4) = quant4_e4m3(v1, s1);
    if (lane == 0) { g_xs[t0] = s0; g_xs[t0 + 1] = s1; }
}

// ---------------------------------------------------------------------------
// Kernel 2: per 128x128 block weight quant. One 256-thread CTA per block.
// ---------------------------------------------------------------------------
__global__ __launch_bounds__(256) void quant_w_kernel(const float* __restrict__ w) {
    int b   = blockIdx.x;          // NE*NBLK*KBLK = 2048 blocks
    int e   = b >> 8;
    int rem = b & 255;
    int nb  = rem >> 4;
    int kb  = rem & 15;

    const size_t base = ((size_t)(e * DOUT + nb * GRP)) * DIN + kb * GRP;
    const float* src = w + base;
    uint8_t* dst = g_wq + base;

    int tid  = threadIdx.x;
    int lane = tid & 31;
    int warp = tid >> 5;

    float a = 0.0f;
#pragma unroll
    for (int i = tid; i < 4096; i += 256) {
        int r = i >> 5, c = i & 31;
        float4 v = *reinterpret_cast<const float4*>(src + (size_t)r * DIN + c * 4);
        a = fmaxf(a, fmaxf(fmaxf(fabsf(v.x), fabsf(v.y)), fmaxf(fabsf(v.z), fabsf(v.w))));
    }
#pragma unroll
    for (int o = 16; o; o >>= 1) a = fmaxf(a, __shfl_xor_sync(0xffffffffu, a, o));

    __shared__ float red[8];
    __shared__ float s_scale;
    if (lane == 0) red[warp] = a;
    __syncthreads();
    if (tid == 0) {
        float m = red[0];
#pragma unroll
        for (int i = 1; i < 8; i++) m = fmaxf(m, red[i]);
        s_scale = fmaxf(m, 1e-12f) / 448.0f;
    }
    __syncthreads();
    float scale = s_scale;

#pragma unroll
    for (int i = tid; i < 4096; i += 256) {
        int r = i >> 5, c = i & 31;
        float4 v = *reinterpret_cast<const float4*>(src + (size_t)r * DIN + c * 4);
        *reinterpret_cast<uint32_t*>(dst + (size_t)r * DIN + c * 4) = quant4_e4m3(v, scale);
    }
    if (tid == 0) g_ws[(e * NBLK + nb) * KBLK + kb] = scale;
}

// ---------------------------------------------------------------------------
// Kernel 3: grouped block-scaled GEMM. 128x128 tile, BK=128 stages, fp8 QMMA,
// SW128-swizzled smem, register-double-buffered fragments, 1 sync/stage.
// ---------------------------------------------------------------------------
#define BM    128
#define BN    128
#define BKS   128                 // K bytes per stage == one scale block
#define STG   3
#define TILEB 16384               // 128 rows x 128 B
#define STAGEB (2 * TILEB)        // A + B tile
#define SMEM_REQ (STG * STAGEB)   // 98304 B

__device__ __forceinline__ void cp16(uint32_t dst, const void* src, int src_bytes) {
    asm volatile("cp.async.cg.shared.global [%0], [%1], 16, %2;\n"
                 :: "r"(dst), "l"(src), "r"(src_bytes) : "memory");
}
__device__ __forceinline__ void ldm_x4(uint32_t r[4], uint32_t addr) {
    asm volatile("ldmatrix.sync.aligned.m8n8.x4.shared.b16 {%0,%1,%2,%3}, [%4];"
                 : "=r"(r[0]), "=r"(r[1]), "=r"(r[2]), "=r"(r[3]) : "r"(addr));
}
__device__ __forceinline__ void mma_fp8(float c[4], const uint32_t a[4], const uint32_t b[2]) {
    asm volatile(
        "mma.sync.aligned.m16n8k32.row.col.f32.e4m3.e4m3.f32 "
        "{%0,%1,%2,%3}, {%4,%5,%6,%7}, {%8,%9}, {%0,%1,%2,%3};"
        : "+f"(c[0]), "+f"(c[1]), "+f"(c[2]), "+f"(c[3])
        : "r"(a[0]), "r"(a[1]), "r"(a[2]), "r"(a[3]), "r"(b[0]), "r"(b[1]));
}
__device__ __forceinline__ uint32_t smem_u32(const void* p) {
    uint32_t a;
    asm("{ .reg .u64 t; cvta.to.shared.u64 t, %1; cvt.u32.u64 %0, t; }" : "=r"(a) : "l"(p));
    return a;
}
// SW128 swizzle, 16B-granular: physical = row*128 + (off16 ^ ((row&7)<<4))
__device__ __forceinline__ uint32_t swz(int row, int off) {
    return (uint32_t)(row * 128 + (off ^ ((row & 7) << 4)));
}

__global__ __launch_bounds__(256, 1) void gemm_kernel(float* __restrict__ out,
                                                      const int* __restrict__ tpe) {
    extern __shared__ __align__(128) uint8_t sm[];
    const uint32_t s0 = smem_u32(sm);

    const int tid  = threadIdx.x;
    const int lane = tid & 31;
    const int wrp  = tid >> 5;
    const int wm   = wrp & 3;   // 4 warps along M (32 rows each)
    const int wn   = wrp >> 2;  // 2 warps along N (64 cols each)

    const int m0 = blockIdx.y * BM;
    const int n0 = blockIdx.x * BN;

    // Expert lookup (prefix sum over 8 counts)
    int accv = 0, e = -1, rs = 0, re = 0;
#pragma unroll
    for (int i = 0; i < NE; i++) {
        int c = tpe[i];
        if (e < 0 && m0 >= accv && m0 < accv + c) { e = i; rs = accv; re = accv + c; }
        accv += c;
    }
    if (e < 0) { e = 0; rs = 0; re = 0; }   // fully zero tile

    const uint8_t* Aptr = g_xq;
    const uint8_t* Bptr = g_wq + (size_t)e * DOUT * DIN;

    // Stage loader: 1024 A + 1024 B 16B chunks; 8 per thread.
    auto load_stage = [&](int kb, int st) {
        const int kc = kb * BKS;
        const uint32_t ab = s0 + st * STAGEB;
        const uint32_t bb = ab + TILEB;
#pragma unroll
        for (int i = 0; i < 4; i++) {
            int cid = tid + 256 * i;          // 0..1023
            int row = cid >> 3;
            int off = (cid & 7) * 16;
            uint32_t sw = swz(row, off);
            int gr = m0 + row;
            cp16(ab + sw, Aptr + (size_t)gr * DIN + kc + off,
                 (gr >= rs && gr < re) ? 16 : 0);
            cp16(bb + sw, Bptr + (size_t)(n0 + row) * DIN + kc + off, 16);
        }
        asm volatile("cp.async.commit_group;\n" ::: "memory");
    };

    // Fragment loaders (mapping identical to the verified R5 kernel)
    auto ldA = [&](int st, int ks, uint32_t af[2][4]) {
        const int k0 = ks * 32;
#pragma unroll
        for (int mi = 0; mi < 2; mi++) {
            int row = wm * 32 + mi * 16 + (lane & 15);
            int cb  = k0 + ((lane >> 4) << 4);
            ldm_x4(af[mi], s0 + st * STAGEB + swz(row, cb));
        }
    };
    auto ldB = [&](int st, int ks, uint32_t bf[8][2]) {
        const int k0 = ks * 32;
#pragma unroll
        for (int nj = 0; nj < 4; nj++) {
            int g  = lane >> 3;
            int n  = wn * 64 + nj * 16 + ((g >> 1) << 3) + (lane & 7);
            int kk = k0 + ((g & 1) << 4);
            uint32_t r[4];
            ldm_x4(r, s0 + st * STAGEB + TILEB + swz(n, kk));
            bf[nj * 2 + 0][0] = r[0]; bf[nj * 2 + 0][1] = r[1];
            bf[nj * 2 + 1][0] = r[2]; bf[nj * 2 + 1][1] = r[3];
        }
    };

    float tot[2][8][4];
#pragma unroll
    for (int mi = 0; mi < 2; mi++)
#pragma unroll
        for (int ni = 0; ni < 8; ni++)
#pragma unroll
            for (int q = 0; q < 4; q++) tot[mi][ni][q] = 0.f;

    const int swbase = (e * NBLK + (n0 >> 7)) * KBLK;
    const int ra0 = m0 + wm * 32 + (lane >> 2);       // mi=0, first row
    // rows for scale lookup: mi*16 + {0,8}

    load_stage(0, 0);
    load_stage(1, 1);

#pragma unroll 1
    for (int kb = 0; kb < KBLK; kb++) {
        const int st = kb % STG;

        asm volatile("cp.async.wait_group 1;\n" ::: "memory");
        __syncthreads();   // stage kb visible; all warps done with stage kb-1

        if (kb + 2 < KBLK) load_stage(kb + 2, (kb + 2) % STG);
        else               asm volatile("cp.async.commit_group;\n" ::: "memory");

        // Prefetch this K-block's scales
        const float swv = g_ws[swbase + kb];
        float sx[2][2];
#pragma unroll
        for (int mi = 0; mi < 2; mi++) {
            sx[mi][0] = g_xs[(ra0 + mi * 16) * KBLK + kb] * swv;
            sx[mi][1] = g_xs[(ra0 + mi * 16 + 8) * KBLK + kb] * swv;
        }

        float par[2][8][4];
#pragma unroll
        for (int mi = 0; mi < 2; mi++)
#pragma unroll
            for (int ni = 0; ni < 8; ni++)
#pragma unroll
                for (int q = 0; q < 4; q++) par[mi][ni][q] = 0.f;

        uint32_t af[2][2][4];
        uint32_t bf[2][8][2];
        ldA(st, 0, af[0]);
        ldB(st, 0, bf[0]);

#pragma unroll
        for (int ks = 0; ks < 4; ks++) {
            const int cb = ks & 1;
            if (ks < 3) {                 // prefetch next k-step's fragments
                ldA(st, ks + 1, af[cb ^ 1]);
                ldB(st, ks + 1, bf[cb ^ 1]);
            }
#pragma unroll
            for (int mi = 0; mi < 2; mi++)
#pragma unroll
                for (int ni = 0; ni < 8; ni++)
                    mma_fp8(par[mi][ni], af[cb][mi], bf[cb][ni]);
        }

        // Fold per-K-block scales into fp32 totals
#pragma unroll
        for (int mi = 0; mi < 2; mi++)
#pragma unroll
            for (int ni = 0; ni < 8; ni++) {
                tot[mi][ni][0] = fmaf(par[mi][ni][0], sx[mi][0], tot[mi][ni][0]);
                tot[mi][ni][1] = fmaf(par[mi][ni][1], sx[mi][0], tot[mi][ni][1]);
                tot[mi][ni][2] = fmaf(par[mi][ni][2], sx[mi][1], tot[mi][ni][2]);
                tot[mi][ni][3] = fmaf(par[mi][ni][3], sx[mi][1], tot[mi][ni][3]);
            }
    }

    // Epilogue: fp32 stores; rows outside this tile's expert range get zeros
    // (grid covers all of out, so no memset is needed).
#pragma unroll
    for (int mi = 0; mi < 2; mi++) {
        int r0 = m0 + wm * 32 + mi * 16 + (lane >> 2);
        int r1 = r0 + 8;
        bool in0 = (r0 >= rs && r0 < re);
        bool in1 = (r1 >= rs && r1 < re);
#pragma unroll
        for (int ni = 0; ni < 8; ni++) {
            int col = n0 + wn * 64 + ni * 8 + ((lane & 3) << 1);
            float2 v0 = {in0 ? tot[mi][ni][0] : 0.f, in0 ? tot[mi][ni][1] : 0.f};
            float2 v1 = {in1 ? tot[mi][ni][2] : 0.f, in1 ? tot[mi][ni][3] : 0.f};
            *reinterpret_cast<float2*>(out + (size_t)r0 * DOUT + col) = v0;
            *reinterpret_cast<float2*>(out + (size_t)r1 * DOUT + col) = v1;
        }
    }
}

// ---------------------------------------------------------------------------
extern "C" void kernel_launch(void* const* d_in, const int* in_sizes, int n_in,
                              void* d_out, int out_size) {
    const float* x   = (const float*)d_in[0];
    const float* w   = (const float*)d_in[1];
    const int*   tpe = (const int*)d_in[2];
    float* out = (float*)d_out;

    cudaFuncSetAttribute(gemm_kernel, cudaFuncAttributeMaxDynamicSharedMemorySize, SMEM_REQ);

    quant_x_kernel<<<SEQ * KBLK / 16, 256>>>(x);
    quant_w_kernel<<<NE * NBLK * KBLK, 256>>>(w);
    gemm_kernel<<<dim3(DOUT / BN, SEQ / BM), 256, SMEM_REQ>>>(out, tpe);
}